// round 2
// baseline (speedup 1.0000x reference)
#include <cuda_runtime.h>

// Dense_RBS_density_3D: rho_out = W rho W^T, W = product of 39 sparse Givens
// layers on the C(40,2)=780-dim weight-2 basis. Kernel K(M) = (M W^T)^T = W M^T,
// so K(K(rho)) = W rho W^T. Two launches with a private scratch between.
//
// Layout redesign vs R1:
//  - smem tile is column-major [col][20 rows] -> rotations use LDS.128/STS.128
//    (4 rows per instr), conflict-free by k=(5c+q) mod 8 analysis.
//  - 62.4 KB tiles -> 3 CTAs/SM (vs 1), phases overlap across CTAs.
//  - scratch stored as 20x20 transposed blocks: pass1 writes contiguous,
//    pass2 reads contiguous (100% coalesced both ways).

#define DD      780
#define NGATES  39
#define NPAIRS  38
#define NBATCH  64
#define RR      20            // rows per tile
#define NT      39            // DD / RR
#define NQ      5             // RR / 4 row-quads
#define THREADS 256
#define TILE_FLOATS (DD * RR) // 15600
#define CHUNK   (RR * RR)     // 400
#define CHUNK4  (CHUNK / 4)   // 100

__device__ float g_tmp[(size_t)NBATCH * DD * DD];  // 155.7 MB blocked scratch

__device__ __forceinline__ int pair_rank(int p, int q) {  // p < q, 40 qubits
    return p * 39 - (p * (p - 1)) / 2 + (q - p - 1);
}

template <bool FIRST>
__global__ __launch_bounds__(THREADS, 3)
void rbs_kernel(const float* __restrict__ in, float* __restrict__ out,
                const float* __restrict__ angles)
{
    extern __shared__ float tile[];                  // [780 cols][20 rows]
    __shared__ float   s_cos[NGATES], s_sin[NGATES];
    __shared__ ushort2 s_off[NGATES * NPAIRS];       // byte offsets i*80, j*80

    const int tid = threadIdx.x;
    const int b   = blockIdx.x / NT;
    const int t   = blockIdx.x - b * NT;

    if (tid < NGATES) {
        float th = angles[tid];
        s_cos[tid] = cosf(th);
        s_sin[tid] = sinf(th);
    }
    for (int n = tid; n < NGATES * NPAIRS; n += THREADS) {
        int g = n / NPAIRS, p = n - g * NPAIRS;
        int x = p + (p >= g ? 2 : 0);                      // qubit != g, g+1
        int i = (x < g)     ? pair_rank(x, g)     : pair_rank(g, x);     // {g,x}
        int j = (x < g + 1) ? pair_rank(x, g + 1) : pair_rank(g + 1, x); // {g+1,x}
        s_off[n] = make_ushort2((unsigned short)(i * (RR * 4)),
                                (unsigned short)(j * (RR * 4)));
    }

    // ---------- load ----------
    if (FIRST) {
        // rho rows [20t, 20t+20): coalesced row reads, transpose into tile
        const float* src = in + (size_t)b * DD * DD + (size_t)t * RR * DD;
        for (int n = tid; n < NQ * DD; n += THREADS) {
            int q = n / DD, c = n - q * DD;              // lanes: consecutive c
            float v0 = src[(size_t)(4 * q + 0) * DD + c];
            float v1 = src[(size_t)(4 * q + 1) * DD + c];
            float v2 = src[(size_t)(4 * q + 2) * DD + c];
            float v3 = src[(size_t)(4 * q + 3) * DD + c];
            *(float4*)&tile[c * RR + 4 * q] = make_float4(v0, v1, v2, v3);
        }
    } else {
        // blocked scratch: for t1 in [0,39): chunk (b, t1, t) is contiguous
        const float* zb = in + (size_t)b * DD * DD;
        for (int n = tid; n < NT * CHUNK4; n += THREADS) {
            int t1  = n / CHUNK4;
            int rem = n - t1 * CHUNK4;
            int r   = rem / NQ;            // r_local 0..19
            int c4  = rem - r * NQ;        // c_local quad 0..4
            float4 v = *(const float4*)(zb + ((size_t)t1 * NT + t) * CHUNK
                                           + r * RR + 4 * c4);
            *(float4*)&tile[(t1 * RR + r) * RR + 4 * c4] = v;
        }
    }
    __syncthreads();

    // ---------- rotate: 39 gates, fixed (pair, quad) per thread ----------
    {
        char* tb = (char*)tile;
        const int  p      = tid / NQ;                 // pair 0..37
        const int  qb     = (tid - p * NQ) * 16;      // quad byte offset
        const bool active = (tid < NPAIRS * NQ);      // 190 workers
        #pragma unroll 1
        for (int g = 0; g < NGATES; g++) {
            if (active) {
                float c = s_cos[g], s = s_sin[g];
                ushort2 off = s_off[g * NPAIRS + p];
                float4* pi = (float4*)(tb + off.x + qb);
                float4* pj = (float4*)(tb + off.y + qb);
                float4 xi = *pi, xj = *pj, ni, nj;
                ni.x = c * xi.x - s * xj.x;  nj.x = s * xi.x + c * xj.x;
                ni.y = c * xi.y - s * xj.y;  nj.y = s * xi.y + c * xj.y;
                ni.z = c * xi.z - s * xj.z;  nj.z = s * xi.z + c * xj.z;
                ni.w = c * xi.w - s * xj.w;  nj.w = s * xi.w + c * xj.w;
                *pi = ni; *pj = nj;
            }
            __syncthreads();
        }
    }

    // ---------- store ----------
    if (FIRST) {
        // write 20x20 transposed chunks, fully contiguous/coalesced
        float* zb = out + ((size_t)b * NT + t) * TILE_FLOATS;
        for (int n = tid; n < TILE_FLOATS; n += THREADS) {
            int t2 = n / CHUNK;
            int m  = n - t2 * CHUNK;
            int r  = m / RR;               // r_local (chunk-major)
            int cl = m - r * RR;           // c_local
            zb[n] = tile[(t2 * RR + cl) * RR + r];
        }
    } else {
        // final transposed store: out[b][c][20t + row], float4 over rows
        float* dst = out + (size_t)b * DD * DD + t * RR;
        for (int n = tid; n < DD * NQ; n += THREADS) {
            int c  = n / NQ;
            int r4 = n - c * NQ;
            float4 v = *(float4*)&tile[c * RR + 4 * r4];
            *(float4*)(dst + (size_t)c * DD + 4 * r4) = v;
        }
    }
}

extern "C" void kernel_launch(void* const* d_in, const int* in_sizes, int n_in,
                              void* d_out, int out_size) {
    const float* input_state = (const float*)d_in[0];  // [64,780,780] f32
    const float* angles      = (const float*)d_in[1];  // [39] f32
    float* out = (float*)d_out;

    const int smem = TILE_FLOATS * sizeof(float);      // 62,400 B
    static bool attr_done = false;
    cudaFuncSetAttribute(rbs_kernel<true>,
                         cudaFuncAttributeMaxDynamicSharedMemorySize, smem);
    cudaFuncSetAttribute(rbs_kernel<false>,
                         cudaFuncAttributeMaxDynamicSharedMemorySize, smem);
    (void)attr_done;

    dim3 grid(NBATCH * NT);   // 2496 blocks
    rbs_kernel<true ><<<grid, THREADS, smem>>>(input_state, g_tmp, angles);
    rbs_kernel<false><<<grid, THREADS, smem>>>(g_tmp, out, angles);
}

// round 3
// speedup vs baseline: 5.4661x; 5.4661x over previous
#include <cuda_runtime.h>

// Dense_RBS_density_3D: rho_out = W rho W^T, W = product of 39 sparse Givens
// layers (38 disjoint 2x2 rotations each) on the C(40,2)=780-dim basis.
// K(M) = (M W^T)^T = W M^T applied twice => W rho W^T. Two launches, private
// __device__ scratch between. R1-proven geometry: 512 threads, 65-row
// row-major smem tiles (stride 781), 768 blocks. R3 change: rotate loop uses
// a FIXED per-thread (pair, 5-rows) assignment -> no per-item index math,
// 5-way ILP, unrolled.

#define DD      780       // C(40,2)
#define NGATES  39
#define NPAIRS  38
#define NBATCH  64
#define RROWS   65        // rows per tile (780 = 65 * 12)
#define NTILES  12
#define STRIDE  781       // odd padded row stride -> conflict-free smem
#define THREADS 512
#define NSLOTS  13        // row slots; 13 * 5 = 65 rows
#define ACTIVE  (NPAIRS * NSLOTS)   // 494 rotation workers

__device__ float g_tmp[(size_t)NBATCH * DD * DD];  // 155.7 MB scratch

// lexicographic rank of pair (p,q), p<q, over 40 qubits
__device__ __forceinline__ int pair_rank(int p, int q) {
    return p * 39 - (p * (p - 1)) / 2 + (q - p - 1);
}

__device__ __forceinline__ void rbs_body(const float* __restrict__ in,
                                         float* __restrict__ out,
                                         const float* __restrict__ angles) {
    extern __shared__ float tile[];            // RROWS * STRIDE floats
    __shared__ float   s_cos[NGATES], s_sin[NGATES];
    __shared__ ushort2 s_off[NGATES * NPAIRS]; // byte offsets (i*4, j*4)

    const int tid = threadIdx.x;
    const int b   = blockIdx.x / NTILES;
    const int t   = blockIdx.x - b * NTILES;
    const int r0  = t * RROWS;

    if (tid < NGATES) {
        float th = angles[tid];
        s_cos[tid] = cosf(th);
        s_sin[tid] = sinf(th);
    }
    for (int n = tid; n < NGATES * NPAIRS; n += THREADS) {
        int g = n / NPAIRS;
        int p = n - g * NPAIRS;
        int x = p + (p >= g ? 2 : 0);                       // qubit != g, g+1
        int i = (x < g)     ? pair_rank(x, g)     : pair_rank(g, x);     // {g,x}
        int j = (x < g + 1) ? pair_rank(x, g + 1) : pair_rank(g + 1, x); // {g+1,x}
        s_off[n] = make_ushort2((unsigned short)(i * 4), (unsigned short)(j * 4));
    }

    // ---------- load: rows r0..r0+64 of batch b, coalesced float4 ----------
    const float* src = in + (size_t)b * DD * DD + (size_t)r0 * DD;
    #pragma unroll 4
    for (int n = tid; n < RROWS * (DD / 4); n += THREADS) {
        int row = n / (DD / 4);
        int c4  = n - row * (DD / 4);
        float4 v = __ldg((const float4*)(src + (size_t)row * DD) + c4);
        float* d = &tile[row * STRIDE + c4 * 4];
        d[0] = v.x; d[1] = v.y; d[2] = v.z; d[3] = v.w;
    }
    __syncthreads();

    // ---------- rotate: fixed (pair, rows) per thread ----------
    {
        const int  p      = tid / NSLOTS;              // pair 0..37
        const int  slot   = tid - p * NSLOTS;          // 0..12
        const bool active = (tid < ACTIVE);
        // 5 fixed row base pointers (rows slot*5 .. slot*5+4)
        char* row0 = (char*)&tile[(slot * 5 + 0) * STRIDE];
        char* row1 = (char*)&tile[(slot * 5 + 1) * STRIDE];
        char* row2 = (char*)&tile[(slot * 5 + 2) * STRIDE];
        char* row3 = (char*)&tile[(slot * 5 + 3) * STRIDE];
        char* row4 = (char*)&tile[(slot * 5 + 4) * STRIDE];

        #pragma unroll 1
        for (int g = 0; g < NGATES; g++) {
            if (active) {
                const float cg = s_cos[g], sg = s_sin[g];
                const ushort2 off = s_off[g * NPAIRS + p];
                const int oi = off.x, oj = off.y;
                #define ROT(RP)  {                                   \
                    float* bi = (float*)((RP) + oi);                 \
                    float* bj = (float*)((RP) + oj);                 \
                    float xi = *bi, xj = *bj;                        \
                    *bi = cg * xi - sg * xj;                         \
                    *bj = sg * xi + cg * xj; }
                ROT(row0) ROT(row1) ROT(row2) ROT(row3) ROT(row4)
                #undef ROT
            }
            __syncthreads();
        }
    }

    // ---------- transposed store: out[b, col, r0+row] ----------
    float* dstb = out + (size_t)b * DD * DD + r0;
    #pragma unroll 4
    for (int n = tid; n < DD * RROWS; n += THREADS) {
        int col = n / RROWS;
        int row = n - col * RROWS;
        dstb[(size_t)col * DD + row] = tile[row * STRIDE + col];
    }
}

__global__ __launch_bounds__(THREADS, 1)
void rbs_pass1(const float* __restrict__ in, const float* __restrict__ angles) {
    rbs_body(in, g_tmp, angles);
}

__global__ __launch_bounds__(THREADS, 1)
void rbs_pass2(float* __restrict__ out, const float* __restrict__ angles) {
    rbs_body(g_tmp, out, angles);
}

extern "C" void kernel_launch(void* const* d_in, const int* in_sizes, int n_in,
                              void* d_out, int out_size) {
    const float* input_state = (const float*)d_in[0];  // [64,780,780] f32
    const float* angles      = (const float*)d_in[1];  // [39] f32
    float* out = (float*)d_out;

    const int smem = RROWS * STRIDE * sizeof(float);   // 203,060 B
    cudaFuncSetAttribute(rbs_pass1, cudaFuncAttributeMaxDynamicSharedMemorySize, smem);
    cudaFuncSetAttribute(rbs_pass2, cudaFuncAttributeMaxDynamicSharedMemorySize, smem);

    dim3 grid(NBATCH * NTILES);   // 768 blocks
    rbs_pass1<<<grid, THREADS, smem>>>(input_state, angles);
    rbs_pass2<<<grid, THREADS, smem>>>(out, angles);
}

// round 4
// speedup vs baseline: 6.2695x; 1.1470x over previous
#include <cuda_runtime.h>

// Dense_RBS_density_3D: rho_out = W rho W^T, W = 39 sparse Givens layers
// (38 disjoint 2x2 column rotations each) on the C(40,2)=780-dim basis.
// K(M) = (M W^T)^T = W M^T applied twice => W rho W^T. Two launches with a
// private __device__ scratch between.
//
// R4: rows are independent under column rotations -> each WARP owns 4 rows
// and runs all 39 gates with only __syncwarp() between gates. Only 2 block
// barriers total (after load, before store). Loads front-batched (unroll 8).

#define DD      780
#define NGATES  39
#define NPAIRS  38
#define NBATCH  64
#define RROWS   60            // rows per tile = 15 warps * 4 rows
#define NTILES  13            // 780 / 60
#define STRIDE  781           // odd -> conflict-free transposed smem reads
#define THREADS 512
#define LD4     (RROWS * (DD / 4))   // 11700 float4 loads per tile
#define LD4_FULL ((LD4 / THREADS) * THREADS)  // 11264

__device__ float g_tmp[(size_t)NBATCH * DD * DD];  // 155.7 MB scratch

__device__ __forceinline__ int pair_rank(int p, int q) {  // p<q, 40 qubits
    return p * 39 - (p * (p - 1)) / 2 + (q - p - 1);
}

__device__ __forceinline__ void rbs_body(const float* __restrict__ in,
                                         float* __restrict__ out,
                                         const float* __restrict__ angles) {
    extern __shared__ float tile[];                 // RROWS * STRIDE
    __shared__ float   s_cos[NGATES], s_sin[NGATES];
    __shared__ ushort2 s_off[NGATES * NPAIRS];      // byte offsets (i*4, j*4)

    const int tid = threadIdx.x;
    const int b   = blockIdx.x / NTILES;
    const int t   = blockIdx.x - b * NTILES;
    const int r0  = t * RROWS;

    if (tid < NGATES) {
        float th = angles[tid];
        s_cos[tid] = cosf(th);
        s_sin[tid] = sinf(th);
    }
    for (int n = tid; n < NGATES * NPAIRS; n += THREADS) {
        int g = n / NPAIRS;
        int p = n - g * NPAIRS;
        int x = p + (p >= g ? 2 : 0);                        // qubit != g,g+1
        int i = (x < g)     ? pair_rank(x, g)     : pair_rank(g, x);
        int j = (x < g + 1) ? pair_rank(x, g + 1) : pair_rank(g + 1, x);
        s_off[n] = make_ushort2((unsigned short)(i * 4), (unsigned short)(j * 4));
    }

    // ---------- load: 60 rows, coalesced float4, front-batched ----------
    const float* src = in + (size_t)b * DD * DD + (size_t)r0 * DD;
    {
        #pragma unroll 8
        for (int k = 0; k < LD4_FULL / THREADS; k++) {       // 22 uniform iters
            int n   = tid + k * THREADS;
            int row = n / (DD / 4);
            int c4  = n - row * (DD / 4);
            float4 v = __ldg((const float4*)(src + (size_t)row * DD) + c4);
            float* d = &tile[row * STRIDE + c4 * 4];
            d[0] = v.x; d[1] = v.y; d[2] = v.z; d[3] = v.w;
        }
        int n = tid + LD4_FULL;                              // tail: 436 threads
        if (n < LD4) {
            int row = n / (DD / 4);
            int c4  = n - row * (DD / 4);
            float4 v = __ldg((const float4*)(src + (size_t)row * DD) + c4);
            float* d = &tile[row * STRIDE + c4 * 4];
            d[0] = v.x; d[1] = v.y; d[2] = v.z; d[3] = v.w;
        }
    }
    __syncthreads();

    // ---------- rotate: warp-autonomous, 4 rows per warp, no block bar ----
    {
        const int w    = tid >> 5;
        const int lane = tid & 31;
        if (w < 15) {
            // 5 fixed items per lane: n = 32k+lane, p = n>>2, r = n&3
            char* rp[5]; int pidx[5]; bool act[5];
            #pragma unroll
            for (int k = 0; k < 5; k++) {
                int n   = 32 * k + lane;
                act[k]  = (n < NPAIRS * 4);                  // 152 items
                pidx[k] = n >> 2;
                rp[k]   = (char*)&tile[(4 * w + (n & 3)) * STRIDE];
            }
            #pragma unroll 1
            for (int g = 0; g < NGATES; g++) {
                const float cg = s_cos[g], sg = s_sin[g];
                const ushort2* go = &s_off[g * NPAIRS];
                #pragma unroll
                for (int k = 0; k < 5; k++) {
                    if (act[k]) {
                        ushort2 o = go[pidx[k]];
                        float* bi = (float*)(rp[k] + o.x);
                        float* bj = (float*)(rp[k] + o.y);
                        float xi = *bi, xj = *bj;
                        *bi = cg * xi - sg * xj;
                        *bj = sg * xi + cg * xj;
                    }
                }
                __syncwarp();
            }
        }
    }
    __syncthreads();

    // ---------- transposed store: out[b, col, r0+row], coalesced ----------
    float* dstb = out + (size_t)b * DD * DD + r0;
    #pragma unroll 4
    for (int n = tid; n < DD * RROWS; n += THREADS) {
        int col = n / RROWS;
        int row = n - col * RROWS;
        dstb[(size_t)col * DD + row] = tile[row * STRIDE + col];
    }
}

__global__ __launch_bounds__(THREADS, 1)
void rbs_pass1(const float* __restrict__ in, const float* __restrict__ angles) {
    rbs_body(in, g_tmp, angles);
}

__global__ __launch_bounds__(THREADS, 1)
void rbs_pass2(float* __restrict__ out, const float* __restrict__ angles) {
    rbs_body(g_tmp, out, angles);
}

extern "C" void kernel_launch(void* const* d_in, const int* in_sizes, int n_in,
                              void* d_out, int out_size) {
    const float* input_state = (const float*)d_in[0];  // [64,780,780] f32
    const float* angles      = (const float*)d_in[1];  // [39] f32
    float* out = (float*)d_out;

    const int smem = RROWS * STRIDE * sizeof(float);   // 187,440 B
    cudaFuncSetAttribute(rbs_pass1, cudaFuncAttributeMaxDynamicSharedMemorySize, smem);
    cudaFuncSetAttribute(rbs_pass2, cudaFuncAttributeMaxDynamicSharedMemorySize, smem);

    dim3 grid(NBATCH * NTILES);   // 832 blocks
    rbs_pass1<<<grid, THREADS, smem>>>(input_state, angles);
    rbs_pass2<<<grid, THREADS, smem>>>(out, angles);
}